// round 12
// baseline (speedup 1.0000x reference)
#include <cuda_runtime.h>
#include <math.h>

#define D 128
#define MAXN 10000
#define MAXE 640000

// Scratch (no allocation allowed -> __device__ globals)
// g_deg is zeroed by mega_kernel after use (zero-init at load), no zero pass.
__device__ int    g_deg[MAXN];
__device__ float  g_deginv[MAXN];
__device__ int    g_start[MAXN];            // exclusive prefix of deg
__device__ int    g_cursor[MAXN];           // running fill cursors
__device__ __align__(16) int2 g_edge[MAXE]; // CSR: {src, coef_bits}

// ---------------------------------------------------------------------------
// Pass 1: in-degree histogram, 4 edges per thread (int4 load of dst).
// E is a multiple of 4 here; guard handles the general tail anyway.
// ---------------------------------------------------------------------------
__global__ void deg_kernel(const int* __restrict__ ei, int E) {
    int i = blockIdx.x * blockDim.x + threadIdx.x;
    int e = i * 4;
    if (e + 3 < E) {
        int4 d4 = *reinterpret_cast<const int4*>(ei + E + e);
        atomicAdd(&g_deg[d4.x], 1);
        atomicAdd(&g_deg[d4.y], 1);
        atomicAdd(&g_deg[d4.z], 1);
        atomicAdd(&g_deg[d4.w], 1);
    } else {
        for (int k = e; k < E; k++) atomicAdd(&g_deg[ei[E + k]], 1);
    }
}

// ---------------------------------------------------------------------------
// Pass 2: single-block exclusive scan over deg -> start, cursor; also deginv.
// ---------------------------------------------------------------------------
__global__ void scan_kernel(int N) {
    __shared__ int s_wsum[32];
    const int tid  = threadIdx.x;
    const int lane = tid & 31;
    const int wid  = tid >> 5;
    const int CH   = (N + 1023) / 1024;
    const int base = tid * CH;

    int sum = 0;
    for (int j = 0; j < CH; j++) {
        int i = base + j;
        if (i < N) sum += g_deg[i];
    }

    int inc = sum;
    #pragma unroll
    for (int off = 1; off < 32; off <<= 1) {
        int v = __shfl_up_sync(0xFFFFFFFF, inc, off);
        if (lane >= off) inc += v;
    }
    if (lane == 31) s_wsum[wid] = inc;
    __syncthreads();

    if (wid == 0) {
        int w = s_wsum[lane];
        int wi = w;
        #pragma unroll
        for (int off = 1; off < 32; off <<= 1) {
            int v = __shfl_up_sync(0xFFFFFFFF, wi, off);
            if (lane >= off) wi += v;
        }
        s_wsum[lane] = wi - w;
    }
    __syncthreads();

    int run = s_wsum[wid] + inc - sum;
    for (int j = 0; j < CH; j++) {
        int i = base + j;
        if (i < N) {
            int d = g_deg[i];
            g_start[i]  = run;
            g_cursor[i] = run;
            g_deginv[i] = rsqrtf((float)d + 1.0f);
            run += d;
        }
    }
}

// ---------------------------------------------------------------------------
// Pass 3: fill CSR buckets, 2 edges per thread (int2/float2 loads).
// One int atomic + one 8B scattered store per edge.
// ---------------------------------------------------------------------------
__global__ void fill_kernel(const int* __restrict__ ei,
                            const float* __restrict__ ew,
                            int E) {
    int i = blockIdx.x * blockDim.x + threadIdx.x;
    int e = i * 2;
    if (e + 1 < E) {
        int2   s2 = *reinterpret_cast<const int2*>(ei + e);
        int2   d2 = *reinterpret_cast<const int2*>(ei + E + e);
        float2 w2 = *reinterpret_cast<const float2*>(ew + e);
        float c0 = g_deginv[s2.x] * w2.x;
        float c1 = g_deginv[s2.y] * w2.y;
        int p0 = atomicAdd(&g_cursor[d2.x], 1);
        int p1 = atomicAdd(&g_cursor[d2.y], 1);
        g_edge[p0] = make_int2(s2.x, __float_as_int(c0));
        g_edge[p1] = make_int2(s2.y, __float_as_int(c1));
    } else if (e < E) {
        int src = ei[e];
        int dst = ei[E + e];
        int pos = atomicAdd(&g_cursor[dst], 1);
        g_edge[pos] = make_int2(src, __float_as_int(g_deginv[src] * ew[e]));
    }
}

// ---------------------------------------------------------------------------
// Pass 4: mega kernel — gather (fp32) + residual + GEMM + GELU + LayerNorm.
// __launch_bounds__(256, 6): cap regs ~42 -> 48 resident warps/SM (75% occ).
// Gather fast path: 4-edge software pipeline (4 LDG.128 in flight, then FMAs).
// ---------------------------------------------------------------------------
__global__ void __launch_bounds__(256, 6)
mega_kernel(const float* __restrict__ x,
            const float* __restrict__ W,
            const float* __restrict__ b,
            const float* __restrict__ gamma,
            const float* __restrict__ beta,
            float* __restrict__ out,
            int N) {
    __shared__ float s_a[8][D];
    __shared__ int   s_src[8][32];
    __shared__ float s_cf[8][32];
    __shared__ float s_sum[8][4];
    __shared__ float s_sq[8][4];

    const int tid  = threadIdx.x;
    const int wid  = tid >> 5;
    const int lane = tid & 31;
    const int row0 = blockIdx.x * 8;
    const float4* xp = reinterpret_cast<const float4*>(x);

    // ---- Phase 1: gather own row ----
    {
        const int row = row0 + wid;
        if (row < N) {
            const int s0   = g_start[row];
            const int dcnt = g_deg[row];
            if (lane == 0) g_deg[row] = 0;   // restore invariant for next call

            float4 acc = make_float4(0.f, 0.f, 0.f, 0.f);

            for (int base = 0; base < dcnt; base += 32) {
                int idx = base + lane;
                if (idx < dcnt) {
                    int2 em = g_edge[s0 + idx];
                    s_src[wid][lane] = em.x;
                    s_cf[wid][lane]  = __int_as_float(em.y);
                }
                __syncwarp();

                int m = dcnt - base;
                if (m >= 32) {
                    #pragma unroll
                    for (int kk = 0; kk < 32; kk += 4) {
                        int sa = s_src[wid][kk + 0];
                        int sb = s_src[wid][kk + 1];
                        int sc = s_src[wid][kk + 2];
                        int sd = s_src[wid][kk + 3];
                        float ca = s_cf[wid][kk + 0];
                        float cb = s_cf[wid][kk + 1];
                        float cc = s_cf[wid][kk + 2];
                        float cd = s_cf[wid][kk + 3];
                        float4 va = xp[(size_t)sa * 32 + lane];
                        float4 vb = xp[(size_t)sb * 32 + lane];
                        float4 vc = xp[(size_t)sc * 32 + lane];
                        float4 vd = xp[(size_t)sd * 32 + lane];
                        acc.x += va.x * ca; acc.y += va.y * ca;
                        acc.z += va.z * ca; acc.w += va.w * ca;
                        acc.x += vb.x * cb; acc.y += vb.y * cb;
                        acc.z += vb.z * cb; acc.w += vb.w * cb;
                        acc.x += vc.x * cc; acc.y += vc.y * cc;
                        acc.z += vc.z * cc; acc.w += vc.w * cc;
                        acc.x += vd.x * cd; acc.y += vd.y * cd;
                        acc.z += vd.z * cd; acc.w += vd.w * cd;
                    }
                } else {
                    for (int k = 0; k < m; k++) {
                        int   s = s_src[wid][k];
                        float c = s_cf[wid][k];
                        float4 v = xp[(size_t)s * 32 + lane];
                        acc.x += v.x * c; acc.y += v.y * c;
                        acc.z += v.z * c; acc.w += v.w * c;
                    }
                }
                __syncwarp();
            }

            float di = g_deginv[row];
            float4 xr = xp[(size_t)row * 32 + lane];
            float* pa = &s_a[wid][lane * 4];
            pa[0] = acc.x * di + xr.x;
            pa[1] = acc.y * di + xr.y;
            pa[2] = acc.z * di + xr.z;
            pa[3] = acc.w * di + xr.w;
        } else {
            float* pa = &s_a[wid][lane * 4];
            pa[0] = pa[1] = pa[2] = pa[3] = 0.f;
        }
    }
    __syncthreads();

    // ---- Phase 2: GEMM ----
    const int col  = tid & 127;
    const int half = tid >> 7;
    const int r0   = half * 4;

    float acc0 = b[col], acc1 = acc0, acc2 = acc0, acc3 = acc0;

    #pragma unroll 8
    for (int k = 0; k < D; k++) {
        float w = W[k * D + col];
        acc0 += s_a[r0 + 0][k] * w;
        acc1 += s_a[r0 + 1][k] * w;
        acc2 += s_a[r0 + 2][k] * w;
        acc3 += s_a[r0 + 3][k] * w;
    }

    float h[4] = {acc0, acc1, acc2, acc3};

    // exact gelu
    #pragma unroll
    for (int r = 0; r < 4; r++) {
        float v = h[r];
        h[r] = 0.5f * v * (1.0f + erff(v * 0.70710678118654752f));
    }

    // ---- Phase 3: LayerNorm ----
    float sum[4], sq[4];
    #pragma unroll
    for (int r = 0; r < 4; r++) { sum[r] = h[r]; sq[r] = h[r] * h[r]; }

    #pragma unroll
    for (int off = 16; off > 0; off >>= 1) {
        #pragma unroll
        for (int r = 0; r < 4; r++) {
            sum[r] += __shfl_xor_sync(0xFFFFFFFF, sum[r], off);
            sq[r]  += __shfl_xor_sync(0xFFFFFFFF, sq[r], off);
        }
    }
    const int wih = (tid >> 5) & 3;
    if (lane == 0) {
        #pragma unroll
        for (int r = 0; r < 4; r++) {
            s_sum[r0 + r][wih] = sum[r];
            s_sq[r0 + r][wih]  = sq[r];
        }
    }
    __syncthreads();

    float g = gamma[col], bt = beta[col];
    #pragma unroll
    for (int r = 0; r < 4; r++) {
        int rr = r0 + r;
        float s = s_sum[rr][0] + s_sum[rr][1] + s_sum[rr][2] + s_sum[rr][3];
        float q = s_sq[rr][0]  + s_sq[rr][1]  + s_sq[rr][2]  + s_sq[rr][3];
        float mu  = s * (1.0f / D);
        float var = q * (1.0f / D) - mu * mu;
        float rstd = rsqrtf(var + 1e-5f);
        int row = row0 + rr;
        if (row < N) {
            out[(size_t)row * D + col] = (h[r] - mu) * rstd * g + bt;
        }
    }
}

// ---------------------------------------------------------------------------
// Launch
// Inputs (metadata order): x, edge_index(int32), edge_weight, W, b, gamma, beta
// ---------------------------------------------------------------------------
extern "C" void kernel_launch(void* const* d_in, const int* in_sizes, int n_in,
                              void* d_out, int out_size) {
    const float* x     = (const float*)d_in[0];
    const int*   ei    = (const int*)d_in[1];
    const float* ew    = (const float*)d_in[2];
    const float* W     = (const float*)d_in[3];
    const float* b     = (const float*)d_in[4];
    const float* gamma = (const float*)d_in[5];
    const float* beta  = (const float*)d_in[6];
    float*       out   = (float*)d_out;

    const int N = in_sizes[0] / D;       // 10000
    const int E = in_sizes[2];           // 640000

    int e4 = (E + 3) / 4;
    deg_kernel<<<(e4 + 255) / 256, 256>>>(ei, E);
    scan_kernel<<<1, 1024>>>(N);                       // + deginv + cursors
    int e2 = (E + 1) / 2;
    fill_kernel<<<(e2 + 255) / 256, 256>>>(ei, ew, E);
    mega_kernel<<<(N + 7) / 8, 256>>>(x, W, b, gamma, beta, out, N);
}